// round 5
// baseline (speedup 1.0000x reference)
#include <cuda_runtime.h>
#include <cuda_bf16.h>
#include <math.h>
#include <stdint.h>

#define BATCH 4
#define LSEQ  2048
#define DMOD  1024
#define DST   16
#define KCONV 4
#define DINN  2048
#define MROWS (BATCH*LSEQ)   /* 8192 */

// ---------------- scratch (device globals) -----------------------------------
__device__ __align__(128) __nv_bfloat16 g_xib[(size_t)MROWS * DINN];
__device__ __align__(128) __nv_bfloat16 g_xsb[(size_t)MROWS * DINN];
__device__ __align__(128) float g_bc[(size_t)MROWS * 32];
__device__ __align__(128) float g_hs[(size_t)MROWS * DST];
__device__ __align__(128) float g_At[16*16*16];
__device__ __align__(128) float g_Wred[DMOD*DST];
__device__ __align__(128) float g_bconst[DMOD];
__device__ __align__(128) float g_zero[DMOD];                    // zero-init
__device__ __align__(128) __nv_bfloat16 g_xh[(size_t)MROWS*DMOD], g_xl[(size_t)MROWS*DMOD];
__device__ __align__(128) __nv_bfloat16 g_winh[(size_t)DINN*DMOD];          // Win1 hi
__device__ __align__(128) __nv_bfloat16 g_winTh[(size_t)DMOD*DINN], g_winTl[(size_t)DMOD*DINN]; // Win2^T
__device__ __align__(128) __nv_bfloat16 g_woh[(size_t)DMOD*DINN], g_wol[(size_t)DMOD*DINN];     // Wout
__device__ __align__(128) __nv_bfloat16 g_wcombh[(size_t)DMOD*DMOD], g_wcombl[(size_t)DMOD*DMOD];
__device__ __align__(128) __nv_bfloat16 g_wxh[(size_t)128*DINN];

// ============================ PTX helpers (arch-agnostic) ====================
__device__ __forceinline__ uint32_t smem_u32(const void* p) {
    uint32_t a;
    asm("{ .reg .u64 t; cvta.to.shared.u64 t, %1; cvt.u32.u64 %0, t; }"
        : "=r"(a) : "l"(p));
    return a;
}
__device__ __forceinline__ void cp16(uint32_t s, const void* g) {
    asm volatile("cp.async.cg.shared.global [%0], [%1], 16;" :: "r"(s), "l"(g));
}
#define CP_COMMIT() asm volatile("cp.async.commit_group;" ::: "memory")
template<int N> __device__ __forceinline__ void cp_wait() {
    asm volatile("cp.async.wait_group %0;" :: "n"(N) : "memory");
}
__device__ __forceinline__ void ldsm_x4(uint32_t& r0, uint32_t& r1,
                                        uint32_t& r2, uint32_t& r3, uint32_t a) {
    asm volatile("ldmatrix.sync.aligned.m8n8.x4.shared.b16 {%0,%1,%2,%3}, [%4];"
                 : "=r"(r0), "=r"(r1), "=r"(r2), "=r"(r3) : "r"(a));
}
__device__ __forceinline__ void mma16816(float* c,
    uint32_t a0, uint32_t a1, uint32_t a2, uint32_t a3, uint32_t b0, uint32_t b1) {
    asm volatile(
        "mma.sync.aligned.m16n8k16.row.col.f32.bf16.bf16.f32 "
        "{%0,%1,%2,%3}, {%4,%5,%6,%7}, {%8,%9}, {%0,%1,%2,%3};"
        : "+f"(c[0]), "+f"(c[1]), "+f"(c[2]), "+f"(c[3])
        : "r"(a0), "r"(a1), "r"(a2), "r"(a3), "r"(b0), "r"(b1));
}
__device__ __forceinline__ uint32_t swz(uint32_t bo) { return bo ^ ((bo >> 3) & 0x70); }

// ================== split-bf16 GEMM via mma.sync: C = A @ B^T ================
// MODE 0: split-bf16 out (outh/outl) + bias   MODE 1: fp32 + bias
// MODE 2: bf16 + bias                          MODE 3: fp32 + bias, n<32 only
template<int ROWS>
__device__ __forceinline__ void load_tile_async(const __nv_bfloat16* __restrict__ g,
                                                long row0, int ld, int k0,
                                                uint32_t sb, int tid) {
    #pragma unroll
    for (int t = 0; t < ROWS/32; t++) {
        int idx = tid + t * 256;
        int r = idx >> 3, cv = idx & 7;
        cp16(sb + swz((uint32_t)(r * 128 + cv * 16)),
             g + (row0 + r) * (long)ld + k0 + cv * 8);
    }
}

template<int MODE, int PASSES, int BN_>
__global__ __launch_bounds__(256, 1)
void gemm_mma(const __nv_bfloat16* __restrict__ Ah, const __nv_bfloat16* __restrict__ Al, int lda,
              const __nv_bfloat16* __restrict__ Bh, const __nv_bfloat16* __restrict__ Bl, int ldb,
              const float* __restrict__ bias,
              float* __restrict__ Cout, int ldc,
              __nv_bfloat16* __restrict__ outh, __nv_bfloat16* __restrict__ outl, int ldr,
              int K)
{
    constexpr int ATILE = 16384;
    constexpr int BTILE = BN_ * 128;
    constexpr int OFF_AL = ATILE;
    constexpr int OFF_BH = (PASSES == 3) ? 2*ATILE : ATILE;
    constexpr int OFF_BL = OFF_BH + BTILE;
    constexpr int STAGE  = OFF_BH + ((PASSES == 3) ? 2*BTILE : BTILE);
    constexpr int NF = BN_ / 16;
    constexpr int NB = BN_ / 32;

    extern __shared__ char smem_raw[];
    uint32_t raw = smem_u32(smem_raw);
    const uint32_t sbase = (raw + 1023u) & ~1023u;

    const int tid  = threadIdx.x;
    const int wid  = tid >> 5, lane = tid & 31;
    const int warpM = wid & 3, warpN = wid >> 2;
    const long m0 = (long)blockIdx.y * 128;
    const int  n0 = blockIdx.x * BN_;

    float acc[2][NF][4];
    #pragma unroll
    for (int i = 0; i < 2; i++)
        #pragma unroll
        for (int j = 0; j < NF; j++)
            #pragma unroll
            for (int q = 0; q < 4; q++) acc[i][j][q] = 0.f;

    const int rowA0 = warpM * 32 + (lane & 7) + ((lane >> 3) & 1) * 8;
    const int khA   = (lane >> 4) & 1;
    const int rowB0 = warpN * (BN_/2) + (lane & 7) + ((lane >> 4) & 1) * 8;
    const int khB   = (lane >> 3) & 1;

    const int NC = K / 64;

    auto issue = [&](int c) {
        uint32_t st = sbase + (uint32_t)(c % 3) * STAGE;
        int k0 = c * 64;
        load_tile_async<128>(Ah, m0, lda, k0, st, tid);
        load_tile_async<BN_>(Bh, n0, ldb, k0, st + OFF_BH, tid);
        if (PASSES == 3) {
            load_tile_async<128>(Al, m0, lda, k0, st + OFF_AL, tid);
            load_tile_async<BN_>(Bl, n0, ldb, k0, st + OFF_BL, tid);
        }
        CP_COMMIT();
    };

    issue(0);
    if (NC > 1) issue(1);

    for (int c = 0; c < NC; c++) {
        if (c + 2 < NC)      { issue(c + 2); cp_wait<2>(); }
        else if (c + 1 < NC) { cp_wait<1>(); }
        else                 { cp_wait<0>(); }
        __syncthreads();

        uint32_t st = sbase + (uint32_t)(c % 3) * STAGE;
        #pragma unroll
        for (int ks = 0; ks < 4; ks++) {
            uint32_t ah[2][4], al[2][4], bh[NF][2], bl[NF][2];
            #pragma unroll
            for (int mi = 0; mi < 2; mi++) {
                uint32_t bo = swz((uint32_t)((rowA0 + mi*16) * 128 + ks*32 + khA*16));
                ldsm_x4(ah[mi][0], ah[mi][1], ah[mi][2], ah[mi][3], st + bo);
                if (PASSES == 3)
                    ldsm_x4(al[mi][0], al[mi][1], al[mi][2], al[mi][3], st + OFF_AL + bo);
            }
            #pragma unroll
            for (int nb = 0; nb < NB; nb++) {
                uint32_t bo = swz((uint32_t)((rowB0 + nb*16) * 128 + ks*32 + khB*16));
                ldsm_x4(bh[nb*2][0], bh[nb*2][1], bh[nb*2+1][0], bh[nb*2+1][1],
                        st + OFF_BH + bo);
                if (PASSES == 3)
                    ldsm_x4(bl[nb*2][0], bl[nb*2][1], bl[nb*2+1][0], bl[nb*2+1][1],
                            st + OFF_BL + bo);
            }
            #pragma unroll
            for (int mi = 0; mi < 2; mi++)
                #pragma unroll
                for (int nf = 0; nf < NF; nf++)
                    mma16816(acc[mi][nf], ah[mi][0], ah[mi][1], ah[mi][2], ah[mi][3],
                             bh[nf][0], bh[nf][1]);
            if (PASSES == 3) {
                #pragma unroll
                for (int mi = 0; mi < 2; mi++)
                    #pragma unroll
                    for (int nf = 0; nf < NF; nf++)
                        mma16816(acc[mi][nf], ah[mi][0], ah[mi][1], ah[mi][2], ah[mi][3],
                                 bl[nf][0], bl[nf][1]);
                #pragma unroll
                for (int mi = 0; mi < 2; mi++)
                    #pragma unroll
                    for (int nf = 0; nf < NF; nf++)
                        mma16816(acc[mi][nf], al[mi][0], al[mi][1], al[mi][2], al[mi][3],
                                 bh[nf][0], bh[nf][1]);
            }
        }
        __syncthreads();
    }

    const int g  = lane >> 2, tg = lane & 3;
    #pragma unroll
    for (int mi = 0; mi < 2; mi++) {
        #pragma unroll
        for (int h = 0; h < 2; h++) {
            long m = m0 + warpM * 32 + mi * 16 + h * 8 + g;
            #pragma unroll
            for (int nf = 0; nf < NF; nf++) {
                int n = n0 + warpN * (BN_/2) + nf * 8 + tg * 2;
                if (MODE == 3 && n >= 32) continue;
                float2 bv = *reinterpret_cast<const float2*>(&bias[n]);
                float v0 = acc[mi][nf][h*2+0] + bv.x;
                float v1 = acc[mi][nf][h*2+1] + bv.y;
                if (MODE == 0) {
                    __nv_bfloat16 h0 = __float2bfloat16(v0);
                    __nv_bfloat16 h1 = __float2bfloat16(v1);
                    __nv_bfloat16 l0 = __float2bfloat16(v0 - __bfloat162float(h0));
                    __nv_bfloat16 l1 = __float2bfloat16(v1 - __bfloat162float(h1));
                    long o = m * (long)ldr + n;
                    __nv_bfloat162 ph; ph.x = h0; ph.y = h1;
                    __nv_bfloat162 pl; pl.x = l0; pl.y = l1;
                    *reinterpret_cast<__nv_bfloat162*>(&outh[o]) = ph;
                    *reinterpret_cast<__nv_bfloat162*>(&outl[o]) = pl;
                } else if (MODE == 2) {
                    __nv_bfloat162 p;
                    p.x = __float2bfloat16(v0);
                    p.y = __float2bfloat16(v1);
                    *reinterpret_cast<__nv_bfloat162*>(&outh[m * (long)ldr + n]) = p;
                } else {
                    *reinterpret_cast<float2*>(&Cout[m * (long)ldc + n]) =
                        make_float2(v0, v1);
                }
            }
        }
    }
}

// ---------------- prep kernels -----------------------------------------------
__global__ void prep_at(const float* __restrict__ dt, const float* __restrict__ A,
                        float* __restrict__ At) {
    int t = blockIdx.x * blockDim.x + threadIdx.x;
    if (t < 4096) {
        int j = t >> 8, e = t & 255;
        At[t] = expf(expf(dt[j]) * A[e]);
    }
}

__global__ void prep_wred(const float* __restrict__ Wout, float* __restrict__ Wred) {
    int t = blockIdx.x * blockDim.x + threadIdx.x;
    if (t < DMOD * DST) {
        int m = t >> 4, s = t & 15;
        float sum = 0.f;
        #pragma unroll 8
        for (int r = 0; r < DINN / DST; r++)
            sum += Wout[(size_t)m * DINN + r * DST + s];
        Wred[t] = sum;
    }
}

__global__ void split_f32_v4(const float* __restrict__ src,
                             __nv_bfloat16* __restrict__ hi,
                             __nv_bfloat16* __restrict__ lo, long n4) {
    long t = (long)blockIdx.x * blockDim.x + threadIdx.x;
    if (t < n4) {
        float4 v = reinterpret_cast<const float4*>(src)[t];
        __nv_bfloat16 h0 = __float2bfloat16(v.x), h1 = __float2bfloat16(v.y);
        __nv_bfloat16 h2 = __float2bfloat16(v.z), h3 = __float2bfloat16(v.w);
        __nv_bfloat162 ha; ha.x = h0; ha.y = h1;
        __nv_bfloat162 hb; hb.x = h2; hb.y = h3;
        __nv_bfloat162 la, lb;
        la.x = __float2bfloat16(v.x - __bfloat162float(h0));
        la.y = __float2bfloat16(v.y - __bfloat162float(h1));
        lb.x = __float2bfloat16(v.z - __bfloat162float(h2));
        lb.y = __float2bfloat16(v.w - __bfloat162float(h3));
        reinterpret_cast<__nv_bfloat162*>(hi)[t*2]   = ha;
        reinterpret_cast<__nv_bfloat162*>(hi)[t*2+1] = hb;
        reinterpret_cast<__nv_bfloat162*>(lo)[t*2]   = la;
        reinterpret_cast<__nv_bfloat162*>(lo)[t*2+1] = lb;
    }
}

__global__ void split_hi_v4(const float* __restrict__ src,
                            __nv_bfloat16* __restrict__ hi, long n4) {
    long t = (long)blockIdx.x * blockDim.x + threadIdx.x;
    if (t < n4) {
        float4 v = reinterpret_cast<const float4*>(src)[t];
        __nv_bfloat162 ha; ha.x = __float2bfloat16(v.x); ha.y = __float2bfloat16(v.y);
        __nv_bfloat162 hb; hb.x = __float2bfloat16(v.z); hb.y = __float2bfloat16(v.w);
        reinterpret_cast<__nv_bfloat162*>(hi)[t*2]   = ha;
        reinterpret_cast<__nv_bfloat162*>(hi)[t*2+1] = hb;
    }
}

// transpose + split: src [DINN, DMOD] (row-major) -> th/tl [DMOD, DINN]
__global__ void transpose_split(const float* __restrict__ src,
                                __nv_bfloat16* __restrict__ th,
                                __nv_bfloat16* __restrict__ tl) {
    __shared__ float tile[32][33];
    int di0 = blockIdx.x * 32, dm0 = blockIdx.y * 32;
    int tx = threadIdx.x, ty = threadIdx.y;      // 32 x 8
    #pragma unroll
    for (int i = 0; i < 32; i += 8)
        tile[ty + i][tx] = src[(size_t)(di0 + ty + i) * DMOD + dm0 + tx];
    __syncthreads();
    #pragma unroll
    for (int i = 0; i < 32; i += 8) {
        float v = tile[tx][ty + i];
        __nv_bfloat16 h = __float2bfloat16(v);
        size_t o = (size_t)(dm0 + ty + i) * DINN + di0 + tx;
        th[o] = h;
        tl[o] = __float2bfloat16(v - __bfloat162float(h));
    }
}

// bconst[n] = Wout[n,:] . b2 + b_out[n]   (one warp per n)
__global__ void prep_bconst(const float* __restrict__ Wout,
                            const float* __restrict__ b2,
                            const float* __restrict__ bout,
                            float* __restrict__ bc) {
    int n = blockIdx.x * 8 + (threadIdx.x >> 5);
    int lane = threadIdx.x & 31;
    float s = 0.f;
    for (int k = lane; k < DINN; k += 32)
        s = fmaf(Wout[(size_t)n * DINN + k], b2[k], s);
    #pragma unroll
    for (int o = 16; o; o >>= 1) s += __shfl_xor_sync(0xffffffffu, s, o);
    if (lane == 0) bc[n] = s + bout[n];
}

__global__ void prep_wx(const float* __restrict__ Wx, __nv_bfloat16* __restrict__ o) {
    int t = blockIdx.x * blockDim.x + threadIdx.x;
    if (t < 128 * DINN) {
        int n = t / DINN, k = t % DINN;
        o[t] = __float2bfloat16((n < 32) ? Wx[(size_t)n * DINN + k] : 0.f);
    }
}

// ---------------- depthwise causal conv (K=4) + SiLU, bf16 in/out ------------
__global__ void conv_silu(const __nv_bfloat16* __restrict__ xi,
                          const float* __restrict__ w,
                          const float* __restrict__ cb,
                          __nv_bfloat16* __restrict__ xs)
{
    long t = (long)blockIdx.x * blockDim.x + threadIdx.x;
    if (t >= (long)MROWS * DINN) return;
    int  c  = (int)(t & (DINN - 1));
    long bl = t >> 11;
    int  l  = (int)(bl & (LSEQ - 1));
    long row0 = bl - l;

    float4 wv = *reinterpret_cast<const float4*>(&w[c * 4]);
    float acc = cb[c];
    const float wk[4] = {wv.x, wv.y, wv.z, wv.w};
    #pragma unroll
    for (int k = 0; k < KCONV; k++) {
        int ll = l - (KCONV - 1) + k;
        if (ll >= 0)
            acc = fmaf(__bfloat162float(xi[(size_t)(row0 + ll) * DINN + c]), wk[k], acc);
    }
    float s = 1.f / (1.f + expf(-acc));
    xs[t] = __float2bfloat16(acc * s);
}

// ---------------- sequential nonlinear scan ----------------------------------
__global__ void scan_kernel(const float* __restrict__ bc,
                            const float* __restrict__ At,
                            float* __restrict__ hs)
{
    const int b = blockIdx.x;
    const int i = threadIdx.x;            // 0..15
    const unsigned mask = 0xffffu;
    __shared__ float sAt[16*16*16];
    __shared__ float sBC[64*32];

    for (int t = i; t < 4096/4; t += 16)
        reinterpret_cast<float4*>(sAt)[t] = reinterpret_cast<const float4*>(At)[t];

    const float* bcb = bc + (size_t)b*LSEQ*32;
    float*       hsb = hs + (size_t)b*LSEQ*DST;
    float h = 0.f;

    for (int l0 = 0; l0 < LSEQ; l0 += 64) {
        __syncwarp(mask);
        const float4* src = reinterpret_cast<const float4*>(bcb + (size_t)l0*32);
        for (int t = i; t < 64*32/4; t += 16)
            reinterpret_cast<float4*>(sBC)[t] = src[t];
        __syncwarp(mask);
        for (int ll = 0; ll < 64; ll++) {
            int l = l0 + ll;
            float Bv = sBC[ll*32 + i];
            float Cv = sBC[ll*32 + 16 + i];
            const float* Ar = &sAt[((l & 15) << 8) + (i << 4)];
            float a0 = Cv, a1 = 0.f, a2 = 0.f, a3 = Bv * h;
            #pragma unroll
            for (int j = 0; j < 16; j += 4) {
                a0 = fmaf(Ar[j+0], __shfl_sync(mask, h, j+0), a0);
                a1 = fmaf(Ar[j+1], __shfl_sync(mask, h, j+1), a1);
                a2 = fmaf(Ar[j+2], __shfl_sync(mask, h, j+2), a2);
                a3 = fmaf(Ar[j+3], __shfl_sync(mask, h, j+3), a3);
            }
            h = tanhf((a0 + a1) + (a2 + a3));
            hsb[(size_t)l*DST + i] = h;
        }
    }
}

// ---------------- rank-16 update: out += hs @ Wred^T (fp32) ------------------
__global__ void rank16_add(float* __restrict__ out,
                           const float* __restrict__ hs,
                           const float* __restrict__ Wred) {
    int m = blockIdx.x;
    int t = threadIdx.x;      // 256 threads, 4 outputs each
    __shared__ float sh[16];
    if (t < 16) sh[t] = hs[(size_t)m * 16 + t];
    __syncthreads();
    float4 v = reinterpret_cast<float4*>(out)[(size_t)m * 256 + t];
    int n0 = t * 4;
    #pragma unroll
    for (int s = 0; s < 16; s++) {
        float hv = sh[s];
        v.x = fmaf(hv, Wred[(n0+0)*16 + s], v.x);
        v.y = fmaf(hv, Wred[(n0+1)*16 + s], v.y);
        v.z = fmaf(hv, Wred[(n0+2)*16 + s], v.z);
        v.w = fmaf(hv, Wred[(n0+3)*16 + s], v.w);
    }
    reinterpret_cast<float4*>(out)[(size_t)m * 256 + t] = v;
}

// ---------------- stream / event singletons ----------------------------------
static cudaStream_t side_stream() {
    static cudaStream_t s = []() {
        cudaStream_t t;
        cudaStreamCreateWithFlags(&t, cudaStreamNonBlocking);
        return t;
    }();
    return s;
}
static cudaEvent_t ev(int i) {
    static cudaEvent_t e[2] = { []() { cudaEvent_t x;
        cudaEventCreateWithFlags(&x, cudaEventDisableTiming); return x; }(),
        []() { cudaEvent_t x;
        cudaEventCreateWithFlags(&x, cudaEventDisableTiming); return x; }() };
    return e[i];
}

// ---------------- launcher ----------------------------------------------------
extern "C" void kernel_launch(void* const* d_in, const int* in_sizes, int n_in,
                              void* d_out, int out_size)
{
    const float* x      = (const float*)d_in[0];
    const float* W_in   = (const float*)d_in[1];
    const float* b_in   = (const float*)d_in[2];
    const float* conv_w = (const float*)d_in[3];
    const float* conv_b = (const float*)d_in[4];
    const float* W_x    = (const float*)d_in[5];
    const float* b_x    = (const float*)d_in[6];
    const float* dt     = (const float*)d_in[7];
    const float* A      = (const float*)d_in[8];
    const float* W_out  = (const float*)d_in[10];
    const float* b_out  = (const float*)d_in[11];
    float* out = (float*)d_out;

    float *bc, *hsp, *Atp, *Wred, *bconst, *zerov;
    __nv_bfloat16 *xib, *xsb, *xh, *xl, *winh, *winTh, *winTl, *woh, *wol,
                  *wcombh, *wcombl, *wxh;
    cudaGetSymbolAddress((void**)&xib,    g_xib);
    cudaGetSymbolAddress((void**)&xsb,    g_xsb);
    cudaGetSymbolAddress((void**)&bc,     g_bc);
    cudaGetSymbolAddress((void**)&hsp,    g_hs);
    cudaGetSymbolAddress((void**)&Atp,    g_At);
    cudaGetSymbolAddress((void**)&Wred,   g_Wred);
    cudaGetSymbolAddress((void**)&bconst, g_bconst);
    cudaGetSymbolAddress((void**)&zerov,  g_zero);
    cudaGetSymbolAddress((void**)&xh,     g_xh);
    cudaGetSymbolAddress((void**)&xl,     g_xl);
    cudaGetSymbolAddress((void**)&winh,   g_winh);
    cudaGetSymbolAddress((void**)&winTh,  g_winTh);
    cudaGetSymbolAddress((void**)&winTl,  g_winTl);
    cudaGetSymbolAddress((void**)&woh,    g_woh);
    cudaGetSymbolAddress((void**)&wol,    g_wol);
    cudaGetSymbolAddress((void**)&wcombh, g_wcombh);
    cudaGetSymbolAddress((void**)&wcombl, g_wcombl);
    cudaGetSymbolAddress((void**)&wxh,    g_wxh);

    const int SM_XI  = 3 * (2 * 16384) + 1024;              // MODE2 P1 BN128
    const int SM_BC  = 3 * (16384 + 64*128) + 1024;         // MODE3 P1 BN64
    const int SM_P3  = 3 * (2 * 16384 + 2 * 64*128) + 1024; // P3 BN64
    cudaFuncSetAttribute(gemm_mma<2,1,128>, cudaFuncAttributeMaxDynamicSharedMemorySize, SM_XI);
    cudaFuncSetAttribute(gemm_mma<3,1,64>,  cudaFuncAttributeMaxDynamicSharedMemorySize, SM_BC);
    cudaFuncSetAttribute(gemm_mma<0,3,64>,  cudaFuncAttributeMaxDynamicSharedMemorySize, SM_P3);
    cudaFuncSetAttribute(gemm_mma<1,3,64>,  cudaFuncAttributeMaxDynamicSharedMemorySize, SM_P3);

    cudaStream_t sd = side_stream();
    cudaEvent_t e1 = ev(0), e2 = ev(1);

    // ---- preps / splits (stream 0) ----
    prep_at  <<<16, 256>>>(dt, A, Atp);
    prep_wred<<<64, 256>>>(W_out, Wred);
    prep_wx  <<<(128*DINN + 255)/256, 256>>>(W_x, wxh);
    prep_bconst<<<DMOD/8, 256>>>(W_out, b_in + DINN, b_out, bconst);
    split_f32_v4<<<(int)(((long)MROWS*DMOD/4 + 255)/256), 256>>>(x, xh, xl, (long)MROWS*DMOD/4);
    split_hi_v4 <<<(int)(((long)DINN*DMOD/4 + 255)/256), 256>>>(W_in, winh, (long)DINN*DMOD/4);
    transpose_split<<<dim3(DINN/32, DMOD/32), dim3(32, 8)>>>(W_in + (size_t)DINN*DMOD, winTh, winTl);
    split_f32_v4<<<(int)(((long)DMOD*DINN/4 + 255)/256), 256>>>(W_out, woh, wol, (long)DMOD*DINN/4);

    // ---- xi chain (stream 0) ----
    gemm_mma<2,1,128><<<dim3(DINN/128, MROWS/128), 256, SM_XI>>>(
        xh, nullptr, DMOD, winh, nullptr, DMOD, b_in,
        nullptr, 0, xib, nullptr, DINN, DMOD);
    conv_silu<<<(MROWS*DINN)/256, 256>>>(xib, conv_w, conv_b, xsb);
    gemm_mma<3,1,64><<<dim3(1, MROWS/128), 256, SM_BC>>>(
        xsb, nullptr, DINN, wxh, nullptr, DINN, b_x,
        bc, 32, nullptr, nullptr, 0, DINN);

    // ---- fork scan onto side stream ----
    cudaEventRecord(e1, 0);
    cudaStreamWaitEvent(sd, e1, 0);
    scan_kernel<<<BATCH, 16, 0, sd>>>(bc, Atp, hsp);
    cudaEventRecord(e2, sd);

    // ---- output chain (stream 0, concurrent with scan) ----
    // Wcomb = Wout @ Win2  (1024x1024, K=2048), split-bf16 output
    gemm_mma<0,3,64><<<dim3(DMOD/64, DMOD/128), 256, SM_P3>>>(
        woh, wol, DINN, winTh, winTl, DINN, zerov,
        nullptr, 0, wcombh, wcombl, DMOD, DINN);
    // out = x @ Wcomb^T + bconst  (8192x1024, K=1024)
    gemm_mma<1,3,64><<<dim3(DMOD/64, MROWS/128), 256, SM_P3>>>(
        xh, xl, DMOD, wcombh, wcombl, DMOD, bconst,
        out, DMOD, nullptr, nullptr, 0, DMOD);

    // ---- join, then rank-16 update ----
    cudaStreamWaitEvent(0, e2, 0);
    rank16_add<<<MROWS, 256>>>(out, hsp, Wred);
}

// round 6
// speedup vs baseline: 1.0659x; 1.0659x over previous
#include <cuda_runtime.h>
#include <cuda_bf16.h>
#include <math.h>
#include <stdint.h>

#define BATCH 4
#define LSEQ  2048
#define DMOD  1024
#define DST   16
#define KCONV 4
#define DINN  2048
#define MROWS (BATCH*LSEQ)   /* 8192 */

// ---------------- scratch (device globals) -----------------------------------
__device__ __align__(128) __nv_bfloat16 g_xib[(size_t)MROWS * DINN];
__device__ __align__(128) __nv_bfloat16 g_xsb[(size_t)MROWS * DINN];
__device__ __align__(128) float g_bc[(size_t)MROWS * 32];
__device__ __align__(128) float g_hs[(size_t)MROWS * DST];
__device__ __align__(128) float g_At[16*16*16];
__device__ __align__(128) float g_Wred[DMOD*DST];
__device__ __align__(128) float g_bconst[DMOD];
__device__ __align__(128) float g_zero[DMOD];
__device__ __align__(128) __nv_bfloat16 g_xh[(size_t)MROWS*DMOD], g_xl[(size_t)MROWS*DMOD];
__device__ __align__(128) __nv_bfloat16 g_winh[(size_t)DINN*DMOD];
__device__ __align__(128) __nv_bfloat16 g_winTh[(size_t)DMOD*DINN], g_winTl[(size_t)DMOD*DINN];
__device__ __align__(128) __nv_bfloat16 g_woh[(size_t)DMOD*DINN], g_wol[(size_t)DMOD*DINN];
__device__ __align__(128) __nv_bfloat16 g_wcombh[(size_t)DMOD*DMOD], g_wcombl[(size_t)DMOD*DMOD];
__device__ __align__(128) __nv_bfloat16 g_wxh[(size_t)128*DINN];

// ============================ PTX helpers (arch-agnostic) ====================
__device__ __forceinline__ uint32_t smem_u32(const void* p) {
    uint32_t a;
    asm("{ .reg .u64 t; cvta.to.shared.u64 t, %1; cvt.u32.u64 %0, t; }"
        : "=r"(a) : "l"(p));
    return a;
}
__device__ __forceinline__ void cp16(uint32_t s, const void* g) {
    asm volatile("cp.async.cg.shared.global [%0], [%1], 16;" :: "r"(s), "l"(g));
}
#define CP_COMMIT() asm volatile("cp.async.commit_group;" ::: "memory")
template<int N> __device__ __forceinline__ void cp_wait() {
    asm volatile("cp.async.wait_group %0;" :: "n"(N) : "memory");
}
__device__ __forceinline__ void ldsm_x4(uint32_t& r0, uint32_t& r1,
                                        uint32_t& r2, uint32_t& r3, uint32_t a) {
    asm volatile("ldmatrix.sync.aligned.m8n8.x4.shared.b16 {%0,%1,%2,%3}, [%4];"
                 : "=r"(r0), "=r"(r1), "=r"(r2), "=r"(r3) : "r"(a));
}
__device__ __forceinline__ void mma16816(float* c,
    uint32_t a0, uint32_t a1, uint32_t a2, uint32_t a3, uint32_t b0, uint32_t b1) {
    asm volatile(
        "mma.sync.aligned.m16n8k16.row.col.f32.bf16.bf16.f32 "
        "{%0,%1,%2,%3}, {%4,%5,%6,%7}, {%8,%9}, {%0,%1,%2,%3};"
        : "+f"(c[0]), "+f"(c[1]), "+f"(c[2]), "+f"(c[3])
        : "r"(a0), "r"(a1), "r"(a2), "r"(a3), "r"(b0), "r"(b1));
}
__device__ __forceinline__ float tanh_fast(float x) {
    float r;
    asm("tanh.approx.f32 %0, %1;" : "=f"(r) : "f"(x));
    return r;
}
__device__ __forceinline__ uint32_t swz(uint32_t bo) { return bo ^ ((bo >> 3) & 0x70); }

// ================== split-bf16 GEMM via mma.sync: C = A @ B^T ================
// MODE 0: split-bf16 out + bias   MODE 1: fp32 + bias
// MODE 2: bf16 + bias             MODE 3: fp32 + bias, n<32 only
template<int ROWS>
__device__ __forceinline__ void load_tile_async(const __nv_bfloat16* __restrict__ g,
                                                long row0, int ld, int k0,
                                                uint32_t sb, int tid) {
    #pragma unroll
    for (int t = 0; t < ROWS/32; t++) {
        int idx = tid + t * 256;
        int r = idx >> 3, cv = idx & 7;
        cp16(sb + swz((uint32_t)(r * 128 + cv * 16)),
             g + (row0 + r) * (long)ld + k0 + cv * 8);
    }
}

template<int MODE, int PASSES, int BN_>
__global__ __launch_bounds__(256, 1)
void gemm_mma(const __nv_bfloat16* __restrict__ Ah, const __nv_bfloat16* __restrict__ Al, int lda,
              const __nv_bfloat16* __restrict__ Bh, const __nv_bfloat16* __restrict__ Bl, int ldb,
              const float* __restrict__ bias,
              float* __restrict__ Cout, int ldc,
              __nv_bfloat16* __restrict__ outh, __nv_bfloat16* __restrict__ outl, int ldr,
              int K)
{
    constexpr int ATILE = 16384;
    constexpr int BTILE = BN_ * 128;
    constexpr int OFF_AL = ATILE;
    constexpr int OFF_BH = (PASSES == 3) ? 2*ATILE : ATILE;
    constexpr int OFF_BL = OFF_BH + BTILE;
    constexpr int STAGE  = OFF_BH + ((PASSES == 3) ? 2*BTILE : BTILE);
    constexpr int NF = BN_ / 16;
    constexpr int NB = BN_ / 32;

    extern __shared__ char smem_raw[];
    uint32_t raw = smem_u32(smem_raw);
    const uint32_t sbase = (raw + 1023u) & ~1023u;

    const int tid  = threadIdx.x;
    const int wid  = tid >> 5, lane = tid & 31;
    const int warpM = wid & 3, warpN = wid >> 2;
    const long m0 = (long)blockIdx.y * 128;
    const int  n0 = blockIdx.x * BN_;

    float acc[2][NF][4];
    #pragma unroll
    for (int i = 0; i < 2; i++)
        #pragma unroll
        for (int j = 0; j < NF; j++)
            #pragma unroll
            for (int q = 0; q < 4; q++) acc[i][j][q] = 0.f;

    const int rowA0 = warpM * 32 + (lane & 7) + ((lane >> 3) & 1) * 8;
    const int khA   = (lane >> 4) & 1;
    const int rowB0 = warpN * (BN_/2) + (lane & 7) + ((lane >> 4) & 1) * 8;
    const int khB   = (lane >> 3) & 1;

    const int NC = K / 64;

    auto issue = [&](int c) {
        uint32_t st = sbase + (uint32_t)(c % 3) * STAGE;
        int k0 = c * 64;
        load_tile_async<128>(Ah, m0, lda, k0, st, tid);
        load_tile_async<BN_>(Bh, n0, ldb, k0, st + OFF_BH, tid);
        if (PASSES == 3) {
            load_tile_async<128>(Al, m0, lda, k0, st + OFF_AL, tid);
            load_tile_async<BN_>(Bl, n0, ldb, k0, st + OFF_BL, tid);
        }
        CP_COMMIT();
    };

    issue(0);
    if (NC > 1) issue(1);

    for (int c = 0; c < NC; c++) {
        if (c + 2 < NC)      { issue(c + 2); cp_wait<2>(); }
        else if (c + 1 < NC) { cp_wait<1>(); }
        else                 { cp_wait<0>(); }
        __syncthreads();

        uint32_t st = sbase + (uint32_t)(c % 3) * STAGE;
        #pragma unroll
        for (int ks = 0; ks < 4; ks++) {
            uint32_t ah[2][4], al[2][4], bh[NF][2], bl[NF][2];
            #pragma unroll
            for (int mi = 0; mi < 2; mi++) {
                uint32_t bo = swz((uint32_t)((rowA0 + mi*16) * 128 + ks*32 + khA*16));
                ldsm_x4(ah[mi][0], ah[mi][1], ah[mi][2], ah[mi][3], st + bo);
                if (PASSES == 3)
                    ldsm_x4(al[mi][0], al[mi][1], al[mi][2], al[mi][3], st + OFF_AL + bo);
            }
            #pragma unroll
            for (int nb = 0; nb < NB; nb++) {
                uint32_t bo = swz((uint32_t)((rowB0 + nb*16) * 128 + ks*32 + khB*16));
                ldsm_x4(bh[nb*2][0], bh[nb*2][1], bh[nb*2+1][0], bh[nb*2+1][1],
                        st + OFF_BH + bo);
                if (PASSES == 3)
                    ldsm_x4(bl[nb*2][0], bl[nb*2][1], bl[nb*2+1][0], bl[nb*2+1][1],
                            st + OFF_BL + bo);
            }
            #pragma unroll
            for (int mi = 0; mi < 2; mi++)
                #pragma unroll
                for (int nf = 0; nf < NF; nf++)
                    mma16816(acc[mi][nf], ah[mi][0], ah[mi][1], ah[mi][2], ah[mi][3],
                             bh[nf][0], bh[nf][1]);
            if (PASSES == 3) {
                #pragma unroll
                for (int mi = 0; mi < 2; mi++)
                    #pragma unroll
                    for (int nf = 0; nf < NF; nf++)
                        mma16816(acc[mi][nf], ah[mi][0], ah[mi][1], ah[mi][2], ah[mi][3],
                                 bl[nf][0], bl[nf][1]);
                #pragma unroll
                for (int mi = 0; mi < 2; mi++)
                    #pragma unroll
                    for (int nf = 0; nf < NF; nf++)
                        mma16816(acc[mi][nf], al[mi][0], al[mi][1], al[mi][2], al[mi][3],
                                 bh[nf][0], bh[nf][1]);
            }
        }
        __syncthreads();
    }

    const int g  = lane >> 2, tg = lane & 3;
    #pragma unroll
    for (int mi = 0; mi < 2; mi++) {
        #pragma unroll
        for (int h = 0; h < 2; h++) {
            long m = m0 + warpM * 32 + mi * 16 + h * 8 + g;
            #pragma unroll
            for (int nf = 0; nf < NF; nf++) {
                int n = n0 + warpN * (BN_/2) + nf * 8 + tg * 2;
                if (MODE == 3 && n >= 32) continue;
                float2 bv = *reinterpret_cast<const float2*>(&bias[n]);
                float v0 = acc[mi][nf][h*2+0] + bv.x;
                float v1 = acc[mi][nf][h*2+1] + bv.y;
                if (MODE == 0) {
                    __nv_bfloat16 h0 = __float2bfloat16(v0);
                    __nv_bfloat16 h1 = __float2bfloat16(v1);
                    __nv_bfloat16 l0 = __float2bfloat16(v0 - __bfloat162float(h0));
                    __nv_bfloat16 l1 = __float2bfloat16(v1 - __bfloat162float(h1));
                    long o = m * (long)ldr + n;
                    __nv_bfloat162 ph; ph.x = h0; ph.y = h1;
                    __nv_bfloat162 pl; pl.x = l0; pl.y = l1;
                    *reinterpret_cast<__nv_bfloat162*>(&outh[o]) = ph;
                    *reinterpret_cast<__nv_bfloat162*>(&outl[o]) = pl;
                } else if (MODE == 2) {
                    __nv_bfloat162 p;
                    p.x = __float2bfloat16(v0);
                    p.y = __float2bfloat16(v1);
                    *reinterpret_cast<__nv_bfloat162*>(&outh[m * (long)ldr + n]) = p;
                } else {
                    *reinterpret_cast<float2*>(&Cout[m * (long)ldc + n]) =
                        make_float2(v0, v1);
                }
            }
        }
    }
}

// ---------------- prep kernels -----------------------------------------------
__global__ void prep_at(const float* __restrict__ dt, const float* __restrict__ A,
                        float* __restrict__ At) {
    int t = blockIdx.x * blockDim.x + threadIdx.x;
    if (t < 4096) {
        int j = t >> 8, e = t & 255;
        At[t] = expf(expf(dt[j]) * A[e]);
    }
}

__global__ void prep_wred(const float* __restrict__ Wout, float* __restrict__ Wred) {
    int t = blockIdx.x * blockDim.x + threadIdx.x;
    if (t < DMOD * DST) {
        int m = t >> 4, s = t & 15;
        float sum = 0.f;
        #pragma unroll 8
        for (int r = 0; r < DINN / DST; r++)
            sum += Wout[(size_t)m * DINN + r * DST + s];
        Wred[t] = sum;
    }
}

__global__ void split_f32_v4(const float* __restrict__ src,
                             __nv_bfloat16* __restrict__ hi,
                             __nv_bfloat16* __restrict__ lo, long n4) {
    long t = (long)blockIdx.x * blockDim.x + threadIdx.x;
    if (t < n4) {
        float4 v = reinterpret_cast<const float4*>(src)[t];
        __nv_bfloat16 h0 = __float2bfloat16(v.x), h1 = __float2bfloat16(v.y);
        __nv_bfloat16 h2 = __float2bfloat16(v.z), h3 = __float2bfloat16(v.w);
        __nv_bfloat162 ha; ha.x = h0; ha.y = h1;
        __nv_bfloat162 hb; hb.x = h2; hb.y = h3;
        __nv_bfloat162 la, lb;
        la.x = __float2bfloat16(v.x - __bfloat162float(h0));
        la.y = __float2bfloat16(v.y - __bfloat162float(h1));
        lb.x = __float2bfloat16(v.z - __bfloat162float(h2));
        lb.y = __float2bfloat16(v.w - __bfloat162float(h3));
        reinterpret_cast<__nv_bfloat162*>(hi)[t*2]   = ha;
        reinterpret_cast<__nv_bfloat162*>(hi)[t*2+1] = hb;
        reinterpret_cast<__nv_bfloat162*>(lo)[t*2]   = la;
        reinterpret_cast<__nv_bfloat162*>(lo)[t*2+1] = lb;
    }
}

__global__ void split_hi_v4(const float* __restrict__ src,
                            __nv_bfloat16* __restrict__ hi, long n4) {
    long t = (long)blockIdx.x * blockDim.x + threadIdx.x;
    if (t < n4) {
        float4 v = reinterpret_cast<const float4*>(src)[t];
        __nv_bfloat162 ha; ha.x = __float2bfloat16(v.x); ha.y = __float2bfloat16(v.y);
        __nv_bfloat162 hb; hb.x = __float2bfloat16(v.z); hb.y = __float2bfloat16(v.w);
        reinterpret_cast<__nv_bfloat162*>(hi)[t*2]   = ha;
        reinterpret_cast<__nv_bfloat162*>(hi)[t*2+1] = hb;
    }
}

// transpose + split: src [DINN, DMOD] -> th/tl [DMOD, DINN]
__global__ void transpose_split(const float* __restrict__ src,
                                __nv_bfloat16* __restrict__ th,
                                __nv_bfloat16* __restrict__ tl) {
    __shared__ float tile[32][33];
    int di0 = blockIdx.x * 32, dm0 = blockIdx.y * 32;
    int tx = threadIdx.x, ty = threadIdx.y;
    #pragma unroll
    for (int i = 0; i < 32; i += 8)
        tile[ty + i][tx] = src[(size_t)(di0 + ty + i) * DMOD + dm0 + tx];
    __syncthreads();
    #pragma unroll
    for (int i = 0; i < 32; i += 8) {
        float v = tile[tx][ty + i];
        __nv_bfloat16 h = __float2bfloat16(v);
        size_t o = (size_t)(dm0 + ty + i) * DINN + di0 + tx;
        th[o] = h;
        tl[o] = __float2bfloat16(v - __bfloat162float(h));
    }
}

__global__ void prep_bconst(const float* __restrict__ Wout,
                            const float* __restrict__ b2,
                            const float* __restrict__ bout,
                            float* __restrict__ bc) {
    int n = blockIdx.x * 8 + (threadIdx.x >> 5);
    int lane = threadIdx.x & 31;
    float s = 0.f;
    for (int k = lane; k < DINN; k += 32)
        s = fmaf(Wout[(size_t)n * DINN + k], b2[k], s);
    #pragma unroll
    for (int o = 16; o; o >>= 1) s += __shfl_xor_sync(0xffffffffu, s, o);
    if (lane == 0) bc[n] = s + bout[n];
}

__global__ void prep_wx(const float* __restrict__ Wx, __nv_bfloat16* __restrict__ o) {
    int t = blockIdx.x * blockDim.x + threadIdx.x;
    if (t < 128 * DINN) {
        int n = t / DINN, k = t % DINN;
        o[t] = __float2bfloat16((n < 32) ? Wx[(size_t)n * DINN + k] : 0.f);
    }
}

// ---------------- depthwise causal conv (K=4) + SiLU, bf16 in/out ------------
__global__ void conv_silu(const __nv_bfloat16* __restrict__ xi,
                          const float* __restrict__ w,
                          const float* __restrict__ cb,
                          __nv_bfloat16* __restrict__ xs)
{
    long t = (long)blockIdx.x * blockDim.x + threadIdx.x;
    if (t >= (long)MROWS * DINN) return;
    int  c  = (int)(t & (DINN - 1));
    long bl = t >> 11;
    int  l  = (int)(bl & (LSEQ - 1));
    long row0 = bl - l;

    float4 wv = *reinterpret_cast<const float4*>(&w[c * 4]);
    float acc = cb[c];
    const float wk[4] = {wv.x, wv.y, wv.z, wv.w};
    #pragma unroll
    for (int k = 0; k < KCONV; k++) {
        int ll = l - (KCONV - 1) + k;
        if (ll >= 0)
            acc = fmaf(__bfloat162float(xi[(size_t)(row0 + ll) * DINN + c]), wk[k], acc);
    }
    float s = 1.f / (1.f + expf(-acc));
    xs[t] = __float2bfloat16(acc * s);
}

// ---------------- sequential nonlinear scan ----------------------------------
__global__ void scan_kernel(const float* __restrict__ bc,
                            const float* __restrict__ At,
                            float* __restrict__ hs)
{
    const int b = blockIdx.x;
    const int i = threadIdx.x;            // 0..15
    const unsigned mask = 0xffffu;
    __shared__ float sAt[16*16*16];
    __shared__ float sBC[64*32];

    for (int t = i; t < 4096/4; t += 16)
        reinterpret_cast<float4*>(sAt)[t] = reinterpret_cast<const float4*>(At)[t];

    const float* bcb = bc + (size_t)b*LSEQ*32;
    float*       hsb = hs + (size_t)b*LSEQ*DST;
    float h = 0.f;

    for (int l0 = 0; l0 < LSEQ; l0 += 64) {
        __syncwarp(mask);
        const float4* src = reinterpret_cast<const float4*>(bcb + (size_t)l0*32);
        for (int t = i; t < 64*32/4; t += 16)
            reinterpret_cast<float4*>(sBC)[t] = src[t];
        __syncwarp(mask);
        for (int ll = 0; ll < 64; ll++) {
            int l = l0 + ll;
            float Bv = sBC[ll*32 + i];
            float Cv = sBC[ll*32 + 16 + i];
            const float* Ar = &sAt[((l & 15) << 8) + (i << 4)];
            float a0 = Cv, a1 = 0.f, a2 = 0.f, a3 = Bv * h;
            #pragma unroll
            for (int j = 0; j < 16; j += 4) {
                a0 = fmaf(Ar[j+0], __shfl_sync(mask, h, j+0), a0);
                a1 = fmaf(Ar[j+1], __shfl_sync(mask, h, j+1), a1);
                a2 = fmaf(Ar[j+2], __shfl_sync(mask, h, j+2), a2);
                a3 = fmaf(Ar[j+3], __shfl_sync(mask, h, j+3), a3);
            }
            h = tanh_fast((a0 + a1) + (a2 + a3));
            hsb[(size_t)l*DST + i] = h;
        }
    }
}

// ---------------- rank-16 update: out += hs @ Wred^T (fp32) ------------------
__global__ void rank16_add(float* __restrict__ out,
                           const float* __restrict__ hs,
                           const float* __restrict__ Wred) {
    int m = blockIdx.x;
    int t = threadIdx.x;
    __shared__ float sh[16];
    if (t < 16) sh[t] = hs[(size_t)m * 16 + t];
    __syncthreads();
    float4 v = reinterpret_cast<float4*>(out)[(size_t)m * 256 + t];
    int n0 = t * 4;
    #pragma unroll
    for (int s = 0; s < 16; s++) {
        float hv = sh[s];
        v.x = fmaf(hv, Wred[(n0+0)*16 + s], v.x);
        v.y = fmaf(hv, Wred[(n0+1)*16 + s], v.y);
        v.z = fmaf(hv, Wred[(n0+2)*16 + s], v.z);
        v.w = fmaf(hv, Wred[(n0+3)*16 + s], v.w);
    }
    reinterpret_cast<float4*>(out)[(size_t)m * 256 + t] = v;
}

// ---------------- stream / event singletons ----------------------------------
static cudaStream_t side_stream() {
    static cudaStream_t s = []() {
        cudaStream_t t;
        cudaStreamCreateWithFlags(&t, cudaStreamNonBlocking);
        return t;
    }();
    return s;
}
static cudaEvent_t ev(int i) {
    static cudaEvent_t e[4] = {nullptr, nullptr, nullptr, nullptr};
    if (!e[0])
        for (int k = 0; k < 4; k++)
            cudaEventCreateWithFlags(&e[k], cudaEventDisableTiming);
    return e[i];
}

// ---------------- launcher ----------------------------------------------------
extern "C" void kernel_launch(void* const* d_in, const int* in_sizes, int n_in,
                              void* d_out, int out_size)
{
    const float* x      = (const float*)d_in[0];
    const float* W_in   = (const float*)d_in[1];
    const float* b_in   = (const float*)d_in[2];
    const float* conv_w = (const float*)d_in[3];
    const float* conv_b = (const float*)d_in[4];
    const float* W_x    = (const float*)d_in[5];
    const float* b_x    = (const float*)d_in[6];
    const float* dt     = (const float*)d_in[7];
    const float* A      = (const float*)d_in[8];
    const float* W_out  = (const float*)d_in[10];
    const float* b_out  = (const float*)d_in[11];
    float* out = (float*)d_out;

    float *bcv, *hsp, *Atp, *Wred, *bconst, *zerov;
    __nv_bfloat16 *xib, *xsb, *xh, *xl, *winh, *winTh, *winTl, *woh, *wol,
                  *wcombh, *wcombl, *wxh;
    cudaGetSymbolAddress((void**)&xib,    g_xib);
    cudaGetSymbolAddress((void**)&xsb,    g_xsb);
    cudaGetSymbolAddress((void**)&bcv,    g_bc);
    cudaGetSymbolAddress((void**)&hsp,    g_hs);
    cudaGetSymbolAddress((void**)&Atp,    g_At);
    cudaGetSymbolAddress((void**)&Wred,   g_Wred);
    cudaGetSymbolAddress((void**)&bconst, g_bconst);
    cudaGetSymbolAddress((void**)&zerov,  g_zero);
    cudaGetSymbolAddress((void**)&xh,     g_xh);
    cudaGetSymbolAddress((void**)&xl,     g_xl);
    cudaGetSymbolAddress((void**)&winh,   g_winh);
    cudaGetSymbolAddress((void**)&winTh,  g_winTh);
    cudaGetSymbolAddress((void**)&winTl,  g_winTl);
    cudaGetSymbolAddress((void**)&woh,    g_woh);
    cudaGetSymbolAddress((void**)&wol,    g_wol);
    cudaGetSymbolAddress((void**)&wcombh, g_wcombh);
    cudaGetSymbolAddress((void**)&wcombl, g_wcombl);
    cudaGetSymbolAddress((void**)&wxh,    g_wxh);

    const int SM_XI   = 3 * (2 * 16384) + 1024;               // MODE2 P1 BN128
    const int SM_BC   = 3 * (16384 + 64*128) + 1024;          // MODE3 P1 BN64
    const int SM_P364 = 3 * (2 * 16384 + 2 * 64*128) + 1024;  // P3 BN64 (Wcomb)
    const int SM_P3128= 3 * (4 * 16384) + 1024;               // P3 BN128 (out)
    cudaFuncSetAttribute(gemm_mma<2,1,128>, cudaFuncAttributeMaxDynamicSharedMemorySize, SM_XI);
    cudaFuncSetAttribute(gemm_mma<3,1,64>,  cudaFuncAttributeMaxDynamicSharedMemorySize, SM_BC);
    cudaFuncSetAttribute(gemm_mma<0,3,64>,  cudaFuncAttributeMaxDynamicSharedMemorySize, SM_P364);
    cudaFuncSetAttribute(gemm_mma<1,3,128>, cudaFuncAttributeMaxDynamicSharedMemorySize, SM_P3128);

    cudaStream_t sd = side_stream();
    cudaEvent_t e_fork = ev(0), e_x = ev(1), e_hs = ev(2), e_done = ev(3);

    // ---- fork side stream at capture start ----
    cudaEventRecord(e_fork, 0);
    cudaStreamWaitEvent(sd, e_fork, 0);

    // ==== stream 0: xi chain ====
    split_f32_v4<<<(int)(((long)MROWS*DMOD/4 + 255)/256), 256>>>(x, xh, xl, (long)MROWS*DMOD/4);
    cudaEventRecord(e_x, 0);
    prep_at <<<16, 256>>>(dt, A, Atp);
    split_hi_v4<<<(int)(((long)DINN*DMOD/4 + 255)/256), 256>>>(W_in, winh, (long)DINN*DMOD/4);
    prep_wx <<<(128*DINN + 255)/256, 256>>>(W_x, wxh);

    gemm_mma<2,1,128><<<dim3(DINN/128, MROWS/128), 256, SM_XI>>>(
        xh, nullptr, DMOD, winh, nullptr, DMOD, b_in,
        nullptr, 0, xib, nullptr, DINN, DMOD);
    conv_silu<<<(MROWS*DINN)/256, 256>>>(xib, conv_w, conv_b, xsb);
    gemm_mma<3,1,64><<<dim3(1, MROWS/128), 256, SM_BC>>>(
        xsb, nullptr, DINN, wxh, nullptr, DINN, b_x,
        bcv, 32, nullptr, nullptr, 0, DINN);
    scan_kernel<<<BATCH, 16>>>(bcv, Atp, hsp);
    cudaEventRecord(e_hs, 0);

    // ==== side stream: output chain (independent of xi chain) ====
    split_f32_v4<<<(int)(((long)DMOD*DINN/4 + 255)/256), 256, 0, sd>>>(
        W_out, woh, wol, (long)DMOD*DINN/4);
    transpose_split<<<dim3(DINN/32, DMOD/32), dim3(32, 8), 0, sd>>>(
        W_in + (size_t)DINN*DMOD, winTh, winTl);
    prep_wred<<<64, 256, 0, sd>>>(W_out, Wred);
    prep_bconst<<<DMOD/8, 256, 0, sd>>>(W_out, b_in + DINN, b_out, bconst);

    // Wcomb = Wout @ Win2 (1024x1024, K=2048), split-bf16 out
    gemm_mma<0,3,64><<<dim3(DMOD/64, DMOD/128), 256, SM_P364, sd>>>(
        woh, wol, DINN, winTh, winTl, DINN, zerov,
        nullptr, 0, wcombh, wcombl, DMOD, DINN);
    // out = x @ Wcomb^T + bconst (needs xh/xl)
    cudaStreamWaitEvent(sd, e_x, 0);
    gemm_mma<1,3,128><<<dim3(DMOD/128, MROWS/128), 256, SM_P3128, sd>>>(
        xh, xl, DMOD, wcombh, wcombl, DMOD, bconst,
        out, DMOD, nullptr, nullptr, 0, DMOD);
    // out += hs @ Wred^T (needs scan result)
    cudaStreamWaitEvent(sd, e_hs, 0);
    rank16_add<<<MROWS, 256, 0, sd>>>(out, hsp, Wred);
    cudaEventRecord(e_done, sd);

    // ---- join side stream before capture ends ----
    cudaStreamWaitEvent(0, e_done, 0);
}